// round 17
// baseline (speedup 1.0000x reference)
#include <cuda_runtime.h>
#include <cuda_fp16.h>
#include <cstdint>

#define B_ 16
#define N_ 4096
#define D_ 128
#define M_ 1536
#define MC 64
#define TN 64                          // tokens per CTA (3 CTAs/SM for overlap)
#define NCHUNK 24
#define NTHR 128

#define XROW 136                       // fp16 elems per X smem row (272B, conflict-free ldmatrix)
#define XH_BYTES (TN*XROW*2)           // 17408
#define WPOOL XH_BYTES
#define WBUF_BYTES (MC*XROW*2)         // 17408
#define SMEM_BYTES (WPOOL + 2*WBUF_BYTES)   // 52224; x3 CTAs = 156672 <= 228KB

__device__ unsigned short g_Wh[M_*D_];   // W [m][d] fp16 (rn)

// ---------------- helpers ----------------
__device__ __forceinline__ uint32_t su32(const void* p){
    uint32_t a;
    asm("{.reg .u64 t; cvta.to.shared.u64 t, %1; cvt.u32.u64 %0, t;}" : "=r"(a) : "l"(p));
    return a;
}
__device__ __forceinline__ uint64_t gu64(const void* p){
    uint64_t a; asm("cvta.to.global.u64 %0, %1;" : "=l"(a) : "l"(p)); return a;
}
#define LDSM4(r0,r1,r2,r3,a) \
  asm volatile("ldmatrix.sync.aligned.m8n8.x4.shared.b16 {%0,%1,%2,%3},[%4];" \
    : "=r"(r0),"=r"(r1),"=r"(r2),"=r"(r3) : "r"(a))
#define LDSM4T(r0,r1,r2,r3,a) \
  asm volatile("ldmatrix.sync.aligned.m8n8.x4.trans.shared.b16 {%0,%1,%2,%3},[%4];" \
    : "=r"(r0),"=r"(r1),"=r"(r2),"=r"(r3) : "r"(a))
#define MMA(c,a0,a1,a2,a3,b0,b1) \
  asm volatile("mma.sync.aligned.m16n8k16.row.col.f32.f16.f16.f32 " \
    "{%0,%1,%2,%3},{%4,%5,%6,%7},{%8,%9},{%0,%1,%2,%3};" \
    : "+f"(c[0]),"+f"(c[1]),"+f"(c[2]),"+f"(c[3]) \
    : "r"(a0),"r"(a1),"r"(a2),"r"(a3),"r"(b0),"r"(b1))
#define CP16(s,g) asm volatile("cp.async.cg.shared.global [%0],[%1],16;" :: "r"(s),"l"(g))
#define EX2(r, x) asm("ex2.approx.f32 %0,%1;" : "=f"(r) : "f"(x))

__device__ __forceinline__ uint32_t h2u(__half2 h){ return *(uint32_t*)&h; }

// exp slice for acc tiles (mt, mt+1) -> 4 packed fp16x2 regs (P fragment row kk = mt/2)
#define EXPSLICE(dst, mt) do { \
    float p0,p1,p2,p3, q0,q1,q2,q3; \
    EX2(p0, acc[mt][0]*S2);   EX2(p1, acc[mt][1]*S2); \
    EX2(p2, acc[mt][2]*S2);   EX2(p3, acc[mt][3]*S2); \
    EX2(q0, acc[mt+1][0]*S2); EX2(q1, acc[mt+1][1]*S2); \
    EX2(q2, acc[mt+1][2]*S2); EX2(q3, acc[mt+1][3]*S2); \
    rs0 += p0 + p1 + q0 + q1;  rs1 += p2 + p3 + q2 + q3; \
    (dst)[0] = h2u(__floats2half2_rn(p0, p1)); \
    (dst)[1] = h2u(__floats2half2_rn(p2, p3)); \
    (dst)[2] = h2u(__floats2half2_rn(q0, q1)); \
    (dst)[3] = h2u(__floats2half2_rn(q2, q3)); \
} while(0)

// mem (1,D,M): mem[d*M+m] -> g_Wh [m][d] fp16 rn. Runs once per launch (cheap).
__global__ void prep_kernel(const float* __restrict__ mem) {
    int t = blockIdx.x*256 + threadIdx.x;
    if (t >= M_*D_) return;
    int d = t / M_, m = t - d*M_;
    __half h = __float2half_rn(mem[t]);
    g_Wh[m*D_ + d] = *(unsigned short*)&h;
}

__global__ __launch_bounds__(NTHR,3)
void attn_mma_kernel(const float* __restrict__ x, float* __restrict__ out) {
    extern __shared__ char smem[];
    const uint32_t sbase = su32(smem);
    const int tid  = threadIdx.x;
    const int lane = tid & 31, warp = tid >> 5;
    const int b = blockIdx.y, n0 = blockIdx.x * TN;
    const float S2 = (float)(0.08838834764831845 * 1.4426950408889634); // 1/sqrt(128)*log2(e)

    // ---- load X tile, convert to fp16, store to smem ----
    const float4* xg = (const float4*)(x + ((size_t)b*N_ + n0)*D_);
    #pragma unroll
    for (int it = 0; it < (TN*D_/4)/NTHR; it++) {     // 16 iters
        int i = it*NTHR + tid;
        int row = i >> 5, c4 = i & 31;        // 4 floats at d = c4*4
        float4 v = xg[i];
        __half2 hA = __floats2half2_rn(v.x, v.y);     // x low, y high (k ascending)
        __half2 hB = __floats2half2_rn(v.z, v.w);
        char* p = smem + (size_t)row*(XROW*2) + (size_t)c4*8;
        *(uint2*)p = make_uint2(h2u(hA), h2u(hB));
    }

    // ---- accumulators ----
    float o[16][4];
    #pragma unroll
    for (int i = 0; i < 16; i++) { o[i][0]=0.f; o[i][1]=0.f; o[i][2]=0.f; o[i][3]=0.f; }
    float rs0 = 0.f, rs1 = 0.f;

    // ldmatrix per-thread base offsets
    const int tw = warp * 16;                         // warp 0..3 -> tokens 0..63
    const uint32_t aX = sbase + ((tw + (lane & 15)) * XROW + ((lane >> 4) << 3)) * 2;
    const uint32_t r1off = (((((lane >> 4) << 3) + (lane & 7)) * XROW) + (((lane >> 3) & 1) << 3)) * 2;
    const uint32_t r2off = ((((((lane >> 3) & 1) << 3) + (lane & 7)) * XROW) + ((lane >> 4) << 3)) * 2;

    // ---- W chunk staging (8x CP16 = 128B per thread per chunk) ----
    auto stageW = [&](int ch, int bsel) {
        const unsigned short* sh = g_Wh + (size_t)ch*MC*D_;
        uint32_t wb = sbase + WPOOL + bsel*WBUF_BYTES;
        #pragma unroll
        for (int r = 0; r < 8; r++) {
            int i = r*NTHR + tid;            // 0..1023 16B-chunks
            int row = i >> 4, seg = i & 15;  // seg of 8 fp16
            uint32_t dst = wb + row*(XROW*2) + seg*16;
            CP16(dst, (const void*)gu64(sh + row*D_ + seg*8));
        }
    };

    stageW(0, 0);
    asm volatile("cp.async.commit_group;");

    for (int ch = 0; ch < NCHUNK; ch++) {
        // Single-sync handoff: each warp waits its OWN staging group for W(ch),
        // then one barrier both publishes W(ch) to all warps and guarantees every
        // warp is done reading the buffer W(ch+1) will overwrite (read last iter).
        asm volatile("cp.async.wait_group 0;");
        __syncthreads();
        if (ch + 1 < NCHUNK) {
            stageW(ch + 1, (ch + 1) & 1);
            asm volatile("cp.async.commit_group;");
        }

        const uint32_t wh = sbase + WPOOL + (ch & 1)*WBUF_BYTES;

        // ---- GEMM1: L[token16][m64] = X·WhT ----
        float acc[8][4];
        #pragma unroll
        for (int i = 0; i < 8; i++) { acc[i][0]=0.f; acc[i][1]=0.f; acc[i][2]=0.f; acc[i][3]=0.f; }

        #pragma unroll
        for (int kk = 0; kk < 8; kk++) {
            uint32_t xh0,xh1,xh2,xh3;
            LDSM4(xh0,xh1,xh2,xh3, aX + kk*32);
            #pragma unroll
            for (int mp = 0; mp < 4; mp++) {
                uint32_t bh0,bh1,bh2,bh3;
                LDSM4(bh0,bh1,bh2,bh3, wh + r1off + mp*(16*XROW*2) + kk*32);
                MMA(acc[2*mp],   xh0,xh1,xh2,xh3, bh0,bh1);
                MMA(acc[2*mp+1], xh0,xh1,xh2,xh3, bh2,bh3);
            }
        }

        // ---- fused exp + GEMM2 software pipeline ----
        // GEMM2 kk-slice consumes only Pa(kk); exp-slice kk+1 issues between
        // slice kk's HMMAs so MUFU work hides under in-flight tensor ops.
        uint32_t Pa[2][4];
        EXPSLICE(Pa[0], 0);
        #pragma unroll
        for (int kk = 0; kk < 4; kk++) {
            if (kk < 3) EXPSLICE(Pa[(kk+1)&1], 2*(kk+1));
            const uint32_t* Pc = Pa[kk&1];
            #pragma unroll
            for (int dp = 0; dp < 8; dp++) {
                uint32_t bh0,bh1,bh2,bh3;
                LDSM4T(bh0,bh1,bh2,bh3, wh + r2off + kk*(16*XROW*2) + dp*32);
                MMA(o[2*dp],   Pc[0],Pc[1],Pc[2],Pc[3], bh0,bh1);
                MMA(o[2*dp+1], Pc[0],Pc[1],Pc[2],Pc[3], bh2,bh3);
            }
        }
    }

    // ---- softmax normalize + store ----
    rs0 += __shfl_xor_sync(0xFFFFFFFFu, rs0, 1);
    rs0 += __shfl_xor_sync(0xFFFFFFFFu, rs0, 2);
    rs1 += __shfl_xor_sync(0xFFFFFFFFu, rs1, 1);
    rs1 += __shfl_xor_sync(0xFFFFFFFFu, rs1, 2);
    float ri0 = 1.0f / rs0, ri1 = 1.0f / rs1;

    float* og = out + ((size_t)b*N_ + n0 + tw + (lane >> 2))*D_ + (lane & 3)*2;
    #pragma unroll
    for (int dt = 0; dt < 16; dt++) {
        *(float2*)(og + dt*8)         = make_float2(o[dt][0]*ri0, o[dt][1]*ri0);
        *(float2*)(og + 8*D_ + dt*8)  = make_float2(o[dt][2]*ri1, o[dt][3]*ri1);
    }
}

extern "C" void kernel_launch(void* const* d_in, const int* in_sizes, int n_in,
                              void* d_out, int out_size) {
    const float* x   = (const float*)d_in[0];   // (B, N, D) fp32
    const float* mem = (const float*)d_in[1];   // (1, D, M) fp32
    float* out = (float*)d_out;                 // (B, N, D) fp32

    prep_kernel<<<(M_*D_ + 255)/256, 256>>>(mem);

    cudaFuncSetAttribute(attn_mma_kernel,
                         cudaFuncAttributeMaxDynamicSharedMemorySize, SMEM_BYTES);
    dim3 grid(N_/TN, B_);
    attn_mma_kernel<<<grid, NTHR, SMEM_BYTES>>>(x, out);
}